// round 4
// baseline (speedup 1.0000x reference)
#include <cuda_runtime.h>
#include <cstdint>
#include <math.h>

// ---------------- problem constants ----------------
#define BATCH 2
#define CH    128
#define LL    4096
#define NS    8

#define D1M  128
#define D1I  256
#define DT1R 8
#define DBL1 24
#define D2M  4096
#define D2I  8192
#define DT2R 256
#define DBL2 272      // dt_rank(256) + 2*8

#define NCH  32
#define CLEN 128

// ---------------- scratch ----------------
__device__ __align__(16) float g_xn1[BATCH*LL*D1M];
__device__ __align__(16) float g_xz1[BATCH*LL*2*D1I];
__device__ __align__(16) float g_xc1[BATCH*LL*D1I];
__device__ __align__(16) float g_dbl1[BATCH*LL*DBL1];
__device__ __align__(16) float g_delta1[BATCH*LL*D1I];
__device__ __align__(16) float g_y1[BATCH*LL*D1I];
__device__ __align__(16) float g_out1[BATCH*LL*D1M];
__device__ __align__(16) float g_ckP[BATCH*D1I*NCH*NS];
__device__ __align__(16) float g_ckH[BATCH*D1I*NCH*NS];
__device__ __align__(16) float g_hin[BATCH*D1I*NCH*NS];

__device__ __align__(16) float g_xn2[BATCH*CH*D2M];
__device__ __align__(16) float g_xz2[BATCH*CH*2*D2I];
__device__ __align__(16) float g_xc2[BATCH*CH*D2I];
__device__ __align__(16) float g_dbl2[BATCH*CH*DBL2];
__device__ __align__(16) float g_delta2[BATCH*CH*D2I];
__device__ __align__(16) float g_y2[BATCH*CH*D2I];
__device__ __align__(16) float g_out2[BATCH*CH*D2M];

// ---------------- helpers ----------------
__device__ __forceinline__ uint32_t smem_u32(const void* p) {
    uint32_t a;
    asm("{ .reg .u64 t; cvta.to.shared.u64 t, %1; cvt.u32.u64 %0, t; }" : "=r"(a) : "l"(p));
    return a;
}
__device__ __forceinline__ void cp_async16(uint32_t dst, const void* src, int sz) {
    asm volatile("cp.async.cg.shared.global [%0], [%1], 16, %2;"
                 :: "r"(dst), "l"(src), "r"(sz) : "memory");
}
#define CP_COMMIT() asm volatile("cp.async.commit_group;" ::: "memory")
#define CP_WAIT1()  asm volatile("cp.async.wait_group 1;" ::: "memory")
#define CP_WAIT0()  asm volatile("cp.async.wait_group 0;" ::: "memory")

__device__ __forceinline__ uint32_t f2tf32(float f) {
    uint32_t r;
    asm("cvt.rna.tf32.f32 %0, %1;" : "=r"(r) : "f"(f));
    return r;
}
__device__ __forceinline__ float rnd_tf32(float v) { return __uint_as_float(f2tf32(v)); }

__device__ __forceinline__ void mma_tf32(float* d, const uint32_t* a, const uint32_t* b) {
    asm volatile(
        "mma.sync.aligned.m16n8k8.row.col.f32.tf32.tf32.f32 "
        "{%0,%1,%2,%3}, {%4,%5,%6,%7}, {%8,%9}, {%0,%1,%2,%3};"
        : "+f"(d[0]), "+f"(d[1]), "+f"(d[2]), "+f"(d[3])
        : "r"(a[0]), "r"(a[1]), "r"(a[2]), "r"(a[3]), "r"(b[0]), "r"(b[1]));
}

__device__ __forceinline__ float siluf(float v) { return v / (1.f + __expf(-v)); }
__device__ __forceinline__ float softplusf(float v) { return (v > 20.f) ? v : log1pf(__expf(v)); }

// ======================================================================
// tf32 mma.sync GEMM: C[m, n] = sum_k X[m, k] * W[n, k]
// A-side (X, activations) must be pre-rounded to tf32 at the producer.
// BM=128, BN=4*WN; warp grid 2x4, warp tile 64 x WN.
// grid = (N tiles, M/128 tiles, ksplits); block = 256 threads
// EPI: 0 = store, 1 = atomicAdd (split-K), 2 = softplus(v + bias[n]) store
// ======================================================================
#define SROW 36

template<int EPI, int WN>
__global__ void __launch_bounds__(256, 1)
tf32_gemm(const float* __restrict__ X, const float* __restrict__ W,
          const float* __restrict__ bias, float* __restrict__ C,
          int M, int N, int kLen, int ldx, int ldw, int ldc) {
    constexpr int BN = 4 * WN;
    constexpr int ROWS = 128 + BN;      // A rows + B rows per stage
    constexpr int NB = WN / 8;          // b-fragments per warp
    extern __shared__ float sm[];
    const int tid = threadIdx.x;
    const int wid = tid >> 5, lane = tid & 31;
    const int gid = lane >> 2, tig = lane & 3;
    const int wm = wid >> 2, wn = wid & 3;        // 2 x 4 warp grid
    const int m0 = blockIdx.y * 128, n0 = blockIdx.x * BN;
    const long k0 = (long)blockIdx.z * kLen;
    const int nIter = kLen / 32;
    const uint32_t sS = smem_u32(sm);

    float acc[4][NB][4];
    #pragma unroll
    for (int i = 0; i < 4; i++)
        #pragma unroll
        for (int j = 0; j < NB; j++)
            #pragma unroll
            for (int r = 0; r < 4; r++) acc[i][j][r] = 0.f;

    auto load_stage = [&](int buf, long kk) {
        #pragma unroll
        for (int i = 0; i < ROWS / 32; i++) {
            int idx = tid + i * 256;
            int row = idx >> 3, ch = idx & 7;
            uint32_t off = (uint32_t)((buf * ROWS + row) * SROW + ch * 4) * 4u;
            if (row < 128) {
                cp_async16(sS + off, X + (long)(m0 + row) * ldx + kk + ch * 4, 16);
            } else {
                int nr = n0 + row - 128;
                const float* gb = W + (long)(nr < N ? nr : 0) * ldw + kk + ch * 4;
                cp_async16(sS + off, gb, nr < N ? 16 : 0);
            }
        }
    };

    load_stage(0, k0); CP_COMMIT();
    load_stage(1, k0 + 32); CP_COMMIT();

    for (int it = 0; it < nIter; it++) {
        if (it + 1 < nIter) { CP_WAIT1(); } else { CP_WAIT0(); }
        __syncthreads();
        if (it + 2 < nIter) { load_stage((it + 2) % 3, k0 + (long)(it + 2) * 32); CP_COMMIT(); }

        const float* A  = sm + (it % 3) * ROWS * SROW;
        const float* Bp = A + 128 * SROW;
        #pragma unroll
        for (int ks = 0; ks < 4; ks++) {
            uint32_t a[4][4], b[NB][2];
            const int kc = ks * 8 + tig;
            #pragma unroll
            for (int mi = 0; mi < 4; mi++) {
                int r = wm * 64 + mi * 16 + gid;
                a[mi][0] = __float_as_uint(A[r * SROW + kc]);
                a[mi][1] = __float_as_uint(A[(r + 8) * SROW + kc]);
                a[mi][2] = __float_as_uint(A[r * SROW + kc + 4]);
                a[mi][3] = __float_as_uint(A[(r + 8) * SROW + kc + 4]);
            }
            #pragma unroll
            for (int ni = 0; ni < NB; ni++) {
                int rn = wn * WN + ni * 8 + gid;
                b[ni][0] = f2tf32(Bp[rn * SROW + kc]);
                b[ni][1] = f2tf32(Bp[rn * SROW + kc + 4]);
            }
            #pragma unroll
            for (int mi = 0; mi < 4; mi++)
                #pragma unroll
                for (int ni = 0; ni < NB; ni++)
                    mma_tf32(acc[mi][ni], a[mi], b[ni]);
        }
        __syncthreads();
    }

    // epilogue
    #pragma unroll
    for (int mi = 0; mi < 4; mi++) {
        int m = m0 + wm * 64 + mi * 16 + gid;
        #pragma unroll
        for (int ni = 0; ni < NB; ni++) {
            int n = n0 + wn * WN + ni * 8 + tig * 2;
            if (n >= N) continue;
            float* p0 = C + (long)m * ldc + n;
            float* p1 = C + (long)(m + 8) * ldc + n;
            float c0 = acc[mi][ni][0], c1 = acc[mi][ni][1];
            float c2 = acc[mi][ni][2], c3 = acc[mi][ni][3];
            if (EPI == 1) {
                atomicAdd(p0, c0); atomicAdd(p0 + 1, c1);
                atomicAdd(p1, c2); atomicAdd(p1 + 1, c3);
            } else if (EPI == 2) {
                float b0v = bias[n], b1v = bias[n + 1];
                *reinterpret_cast<float2*>(p0) =
                    make_float2(softplusf(c0 + b0v), softplusf(c1 + b1v));
                *reinterpret_cast<float2*>(p1) =
                    make_float2(softplusf(c2 + b0v), softplusf(c3 + b1v));
            } else {
                *reinterpret_cast<float2*>(p0) = make_float2(c0, c1);
                *reinterpret_cast<float2*>(p1) = make_float2(c2, c3);
            }
        }
    }
}

#define GSMEM_BYTES_W(WN) (3 * (128 + 4 * (WN)) * SROW * 4)

// ---------------- LayerNorm 1 (output tf32-rounded) ----------------
__global__ void ln1_kernel(const float* __restrict__ x, const float* __restrict__ g,
                           const float* __restrict__ bta, float* __restrict__ out) {
    int b  = blockIdx.x >> 7;
    int l0 = (blockIdx.x & 127) * 32;
    __shared__ float sm[128 * 33];
    int tid = threadIdx.x;
    #pragma unroll
    for (int i = 0; i < 16; i++) {
        int idx = tid + i * 256;
        int c = idx >> 5, l = idx & 31;
        sm[c * 33 + l] = x[((long)b * CH + c) * LL + l0 + l];
    }
    __syncthreads();
    int warp = tid >> 5, lane = tid & 31;
    for (int t = warp; t < 32; t += 8) {
        float v[4]; float s = 0.f, sq = 0.f;
        #pragma unroll
        for (int j = 0; j < 4; j++) {
            v[j] = sm[(lane + 32 * j) * 33 + t];
            s += v[j]; sq += v[j] * v[j];
        }
        #pragma unroll
        for (int o = 16; o; o >>= 1) {
            s  += __shfl_xor_sync(0xffffffffu, s,  o);
            sq += __shfl_xor_sync(0xffffffffu, sq, o);
        }
        float mu  = s * (1.f / 128.f);
        float var = sq * (1.f / 128.f) - mu * mu;
        float rs  = rsqrtf(var + 1e-5f);
        #pragma unroll
        for (int j = 0; j < 4; j++) {
            int c = lane + 32 * j;
            out[((long)b * LL + l0 + t) * D1M + c] = rnd_tf32((v[j] - mu) * rs * g[c] + bta[c]);
        }
    }
}

// ---------------- LayerNorm 2 (output tf32-rounded) ----------------
__global__ void ln2_kernel(const float* __restrict__ x, const float* __restrict__ g,
                           const float* __restrict__ bta, float* __restrict__ out) {
    long row = blockIdx.x;
    const float* xr = x + row * D2M;
    float* orow = out + row * D2M;
    int tid = threadIdx.x;
    float v[16]; float s = 0.f, sq = 0.f;
    #pragma unroll
    for (int i = 0; i < 16; i++) {
        v[i] = xr[i * 256 + tid];
        s += v[i]; sq += v[i] * v[i];
    }
    #pragma unroll
    for (int o = 16; o; o >>= 1) {
        s  += __shfl_xor_sync(0xffffffffu, s,  o);
        sq += __shfl_xor_sync(0xffffffffu, sq, o);
    }
    __shared__ float ss[8], sqq[8];
    int lane = tid & 31, warp = tid >> 5;
    if (!lane) { ss[warp] = s; sqq[warp] = sq; }
    __syncthreads();
    s = 0.f; sq = 0.f;
    #pragma unroll
    for (int w = 0; w < 8; w++) { s += ss[w]; sq += sqq[w]; }
    float mu  = s * (1.f / 4096.f);
    float var = sq * (1.f / 4096.f) - mu * mu;
    float rs  = rsqrtf(var + 1e-5f);
    #pragma unroll
    for (int i = 0; i < 16; i++) {
        int col = i * 256 + tid;
        orow[col] = rnd_tf32((v[i] - mu) * rs * g[col] + bta[col]);
    }
}

// ---------------- fallback SGEMM (dt1: K=8) ----------------
template<int ACT, bool HASBIAS>
__global__ void sgemm_kernel(const float* __restrict__ X, const float* __restrict__ W,
                             const float* __restrict__ bias, float* __restrict__ out,
                             int M, int N, int K, int lda, int ldc) {
    constexpr int BM = 64, BN = 64, BK = 32, PAD = 4;
    __shared__ float As[BK][BM + PAD];
    __shared__ float Bs[BK][BN + PAD];
    int bm = blockIdx.y * BM, bn = blockIdx.x * BN;
    int tid = threadIdx.x;
    int tx = tid & 15, ty = tid >> 4;
    float acc[4][4] = {};
    for (int k0 = 0; k0 < K; k0 += BK) {
        #pragma unroll
        for (int i = 0; i < 2; i++) {
            int idx = tid + i * 256;
            int row = idx >> 3;
            int kc  = (idx & 7) << 2;
            int k   = k0 + kc;
            float4 va = make_float4(0.f, 0.f, 0.f, 0.f);
            float4 vb = make_float4(0.f, 0.f, 0.f, 0.f);
            if (k < K) {
                int m = bm + row;
                if (m < M) va = *reinterpret_cast<const float4*>(X + (long)m * lda + k);
                int n = bn + row;
                if (n < N) vb = *reinterpret_cast<const float4*>(W + (long)n * K + k);
            }
            As[kc][row] = va.x; As[kc + 1][row] = va.y; As[kc + 2][row] = va.z; As[kc + 3][row] = va.w;
            Bs[kc][row] = vb.x; Bs[kc + 1][row] = vb.y; Bs[kc + 2][row] = vb.z; Bs[kc + 3][row] = vb.w;
        }
        __syncthreads();
        #pragma unroll
        for (int kk = 0; kk < BK; kk++) {
            float4 a = *reinterpret_cast<const float4*>(&As[kk][ty << 2]);
            float4 b = *reinterpret_cast<const float4*>(&Bs[kk][tx << 2]);
            float av[4] = {a.x, a.y, a.z, a.w};
            float bv[4] = {b.x, b.y, b.z, b.w};
            #pragma unroll
            for (int i = 0; i < 4; i++)
                #pragma unroll
                for (int j = 0; j < 4; j++)
                    acc[i][j] += av[i] * bv[j];
        }
        __syncthreads();
    }
    #pragma unroll
    for (int i = 0; i < 4; i++) {
        int m = bm + (ty << 2) + i;
        if (m >= M) continue;
        #pragma unroll
        for (int j = 0; j < 4; j++) {
            int n = bn + (tx << 2) + j;
            if (n >= N) continue;
            float v = acc[i][j];
            if (HASBIAS) v += bias[n];
            if (ACT == 1) v = softplusf(v);
            out[(long)m * ldc + n] = v;
        }
    }
}

// ---------------- causal depthwise conv (K=4) + SiLU (output tf32-rounded) ----------------
__global__ void conv_silu_kernel(const float* __restrict__ xz, const float* __restrict__ w,
                                 const float* __restrict__ bias, float* __restrict__ out,
                                 int Ltok, int dinner) {
    long tid = (long)blockIdx.x * 256 + threadIdx.x;
    long total = (long)BATCH * Ltok * dinner;
    if (tid >= total) return;
    int d = (int)(tid % dinner);
    long t = tid / dinner;
    int l = (int)(t % Ltok);
    int b = (int)(t / Ltok);
    int rowstride = 2 * dinner;
    const float* base = xz + ((long)b * Ltok) * rowstride + d;
    float acc = bias[d];
    #pragma unroll
    for (int k = 0; k < 4; k++) {
        int ll = l - 3 + k;
        if (ll >= 0) acc += base[(long)ll * rowstride] * w[d * 4 + k];
    }
    out[tid] = rnd_tf32(siluf(acc));
}

// ---------------- path-1 scan ----------------
__global__ void scan1_partial(const float* __restrict__ delta, const float* __restrict__ xc,
                              const float* __restrict__ dbl, const float* __restrict__ Alog) {
    int d = threadIdx.x;
    int chunk = blockIdx.x & (NCH - 1);
    int b = blockIdx.x >> 5;
    float A[NS], h[NS], P[NS];
    #pragma unroll
    for (int s = 0; s < NS; s++) { A[s] = -__expf(Alog[d * NS + s]); h[s] = 0.f; P[s] = 1.f; }
    int l0 = chunk * CLEN;
    for (int i = 0; i < CLEN; i++) {
        long t = (long)b * LL + l0 + i;
        float dl = delta[t * D1I + d];
        float xv = xc[t * D1I + d];
        const float* bl = dbl + t * DBL1 + DT1R;
        float dx = dl * xv;
        #pragma unroll
        for (int s = 0; s < NS; s++) {
            float dA = __expf(dl * A[s]);
            h[s] = dA * h[s] + dx * bl[s];
            P[s] *= dA;
        }
    }
    long o = (((long)b * D1I + d) * NCH + chunk) * NS;
    #pragma unroll
    for (int s = 0; s < NS; s++) { g_ckP[o + s] = P[s]; g_ckH[o + s] = h[s]; }
}

__global__ void scan1_carry() {
    int idx = blockIdx.x * 256 + threadIdx.x;
    if (idx >= BATCH * D1I) return;
    long base = (long)idx * NCH * NS;
    float h[NS];
    #pragma unroll
    for (int s = 0; s < NS; s++) h[s] = 0.f;
    for (int c = 0; c < NCH; c++) {
        long o = base + (long)c * NS;
        #pragma unroll
        for (int s = 0; s < NS; s++) {
            g_hin[o + s] = h[s];
            h[s] = g_ckP[o + s] * h[s] + g_ckH[o + s];
        }
    }
}

__global__ void scan1_final(const float* __restrict__ delta, const float* __restrict__ xc,
                            const float* __restrict__ dbl, const float* __restrict__ Alog,
                            const float* __restrict__ Dp, const float* __restrict__ xz,
                            float* __restrict__ y) {
    int d = threadIdx.x;
    int chunk = blockIdx.x & (NCH - 1);
    int b = blockIdx.x >> 5;
    float A[NS], h[NS];
    long hb = (((long)b * D1I + d) * NCH + chunk) * NS;
    #pragma unroll
    for (int s = 0; s < NS; s++) { A[s] = -__expf(Alog[d * NS + s]); h[s] = g_hin[hb + s]; }
    float Dv = Dp[d];
    int l0 = chunk * CLEN;
    for (int i = 0; i < CLEN; i++) {
        long t = (long)b * LL + l0 + i;
        float dl = delta[t * D1I + d];
        float xv = xc[t * D1I + d];
        const float* bl = dbl + t * DBL1 + DT1R;
        float dx = dl * xv;
        float acc = 0.f;
        #pragma unroll
        for (int s = 0; s < NS; s++) {
            float dA = __expf(dl * A[s]);
            h[s] = dA * h[s] + dx * bl[s];
            acc += h[s] * bl[NS + s];
        }
        float z = xz[t * (2 * D1I) + D1I + d];
        y[t * D1I + d] = rnd_tf32((acc + xv * Dv) * siluf(z));
    }
}

// ---------------- path-2 scan ----------------
__global__ void scan2_kernel(const float* __restrict__ delta, const float* __restrict__ xc,
                             const float* __restrict__ dbl, const float* __restrict__ Alog,
                             const float* __restrict__ Dp, const float* __restrict__ xz,
                             float* __restrict__ y) {
    int d = (blockIdx.x & 31) * 256 + threadIdx.x;
    int b = blockIdx.x >> 5;
    float A[NS], h[NS];
    #pragma unroll
    for (int s = 0; s < NS; s++) { A[s] = -__expf(Alog[d * NS + s]); h[s] = 0.f; }
    float Dv = Dp[d];
    for (int l = 0; l < CH; l++) {
        long t = (long)b * CH + l;
        float dl = delta[t * D2I + d];
        float xv = xc[t * D2I + d];
        const float* bl = dbl + t * DBL2 + DT2R;
        float dx = dl * xv;
        float acc = 0.f;
        #pragma unroll
        for (int s = 0; s < NS; s++) {
            float dA = __expf(dl * A[s]);
            h[s] = dA * h[s] + dx * bl[s];
            acc += h[s] * bl[NS + s];
        }
        float z = xz[t * (2 * D2I) + D2I + d];
        y[t * D2I + d] = rnd_tf32((acc + xv * Dv) * siluf(z));
    }
}

// ---------------- combine ----------------
__global__ void combine_kernel(const float* __restrict__ x, float* __restrict__ out) {
    long i = (long)blockIdx.x * 256 + threadIdx.x;
    if (i >= (long)BATCH * CH * LL) return;
    int l = (int)(i % LL);
    long t = i / LL;
    int c = (int)(t % CH);
    int b = (int)(t / CH);
    out[i] = x[i] + g_out2[i] + g_out1[((long)b * LL + l) * D1M + c];
}

// ---------------- launch ----------------
extern "C" void kernel_launch(void* const* d_in, const int* in_sizes, int n_in,
                              void* d_out, int out_size) {
    const float* x        = (const float*)d_in[0];
    const float* ln1_g    = (const float*)d_in[1];
    const float* ln1_b    = (const float*)d_in[2];
    const float* ln2_g    = (const float*)d_in[3];
    const float* ln2_b    = (const float*)d_in[4];
    const float* m1_in_w  = (const float*)d_in[5];
    const float* m1_cw    = (const float*)d_in[6];
    const float* m1_cb    = (const float*)d_in[7];
    const float* m1_xp_w  = (const float*)d_in[8];
    const float* m1_dt_w  = (const float*)d_in[9];
    const float* m1_dt_b  = (const float*)d_in[10];
    const float* m1_Alog  = (const float*)d_in[11];
    const float* m1_D     = (const float*)d_in[12];
    const float* m1_out_w = (const float*)d_in[13];
    const float* m2_in_w  = (const float*)d_in[14];
    const float* m2_cw    = (const float*)d_in[15];
    const float* m2_cb    = (const float*)d_in[16];
    const float* m2_xp_w  = (const float*)d_in[17];
    const float* m2_dt_w  = (const float*)d_in[18];
    const float* m2_dt_b  = (const float*)d_in[19];
    const float* m2_Alog  = (const float*)d_in[20];
    const float* m2_D     = (const float*)d_in[21];
    const float* m2_out_w = (const float*)d_in[22];
    float* out = (float*)d_out;

    float *pxn1, *pxz1, *pxc1, *pdbl1, *pdelta1, *py1, *pout1;
    float *pxn2, *pxz2, *pxc2, *pdbl2, *pdelta2, *py2, *pout2;
    cudaGetSymbolAddress((void**)&pxn1, g_xn1);
    cudaGetSymbolAddress((void**)&pxz1, g_xz1);
    cudaGetSymbolAddress((void**)&pxc1, g_xc1);
    cudaGetSymbolAddress((void**)&pdbl1, g_dbl1);
    cudaGetSymbolAddress((void**)&pdelta1, g_delta1);
    cudaGetSymbolAddress((void**)&py1, g_y1);
    cudaGetSymbolAddress((void**)&pout1, g_out1);
    cudaGetSymbolAddress((void**)&pxn2, g_xn2);
    cudaGetSymbolAddress((void**)&pxz2, g_xz2);
    cudaGetSymbolAddress((void**)&pxc2, g_xc2);
    cudaGetSymbolAddress((void**)&pdbl2, g_dbl2);
    cudaGetSymbolAddress((void**)&pdelta2, g_delta2);
    cudaGetSymbolAddress((void**)&py2, g_y2);
    cudaGetSymbolAddress((void**)&pout2, g_out2);

    cudaFuncSetAttribute(tf32_gemm<0, 32>, cudaFuncAttributeMaxDynamicSharedMemorySize, GSMEM_BYTES_W(32));
    cudaFuncSetAttribute(tf32_gemm<0, 64>, cudaFuncAttributeMaxDynamicSharedMemorySize, GSMEM_BYTES_W(64));
    cudaFuncSetAttribute(tf32_gemm<1, 32>, cudaFuncAttributeMaxDynamicSharedMemorySize, GSMEM_BYTES_W(32));
    cudaFuncSetAttribute(tf32_gemm<1, 64>, cudaFuncAttributeMaxDynamicSharedMemorySize, GSMEM_BYTES_W(64));
    cudaFuncSetAttribute(tf32_gemm<2, 32>, cudaFuncAttributeMaxDynamicSharedMemorySize, GSMEM_BYTES_W(32));

    const int T = 256;
    // memsets first (split-K accumulators)
    cudaMemsetAsync(pdbl2, 0, sizeof(float) * BATCH * CH * DBL2);
    cudaMemsetAsync(pout2, 0, sizeof(float) * BATCH * CH * D2M);

    // k0
    ln1_kernel<<<BATCH * (LL / 32), T>>>(x, ln1_g, ln1_b, pxn1);
    // k1
    ln2_kernel<<<BATCH * CH, T>>>(x, ln2_g, ln2_b, pxn2);
    // k2: in1: xz1[8192, 512] = xn1 @ in_w^T
    tf32_gemm<0, 32><<<dim3(4, 64, 1), 256, GSMEM_BYTES_W(32)>>>(
        pxn1, m1_in_w, nullptr, pxz1, BATCH * LL, 2 * D1I, D1M, D1M, D1M, 2 * D1I);
    // k3
    conv_silu_kernel<<<(BATCH * LL * D1I + T - 1) / T, T>>>(pxz1, m1_cw, m1_cb, pxc1, LL, D1I);
    // k4: xp1: dbl1[8192, 24] = xc1 @ xp_w^T
    tf32_gemm<0, 32><<<dim3(1, 64, 1), 256, GSMEM_BYTES_W(32)>>>(
        pxc1, m1_xp_w, nullptr, pdbl1, BATCH * LL, DBL1, D1I, D1I, D1I, DBL1);
    // k5 (PROFILED): in2: xz2[256, 16384] = xn2 @ in_w^T
    tf32_gemm<0, 64><<<dim3(64, 2, 1), 256, GSMEM_BYTES_W(64)>>>(
        pxn2, m2_in_w, nullptr, pxz2, BATCH * CH, 2 * D2I, D2M, D2M, D2M, 2 * D2I);

    // ---- rest of path 1 ----
    sgemm_kernel<1, true><<<dim3((D1I + 63) / 64, (BATCH * LL) / 64), T>>>(
        pdbl1, m1_dt_w, m1_dt_b, pdelta1, BATCH * LL, D1I, DT1R, DBL1, D1I);
    scan1_partial<<<BATCH * NCH, D1I>>>(pdelta1, pxc1, pdbl1, m1_Alog);
    scan1_carry<<<(BATCH * D1I + T - 1) / T, T>>>();
    scan1_final<<<BATCH * NCH, D1I>>>(pdelta1, pxc1, pdbl1, m1_Alog, m1_D, pxz1, py1);
    tf32_gemm<0, 32><<<dim3(1, 64, 1), 256, GSMEM_BYTES_W(32)>>>(
        py1, m1_out_w, nullptr, pout1, BATCH * LL, D1M, D1I, D1I, D1I, D1M);

    // ---- rest of path 2 ----
    conv_silu_kernel<<<(BATCH * CH * D2I + T - 1) / T, T>>>(pxz2, m2_cw, m2_cb, pxc2, CH, D2I);
    // xp2: dbl2[256, 272] split-K=16 atomic
    tf32_gemm<1, 32><<<dim3(3, 2, 16), 256, GSMEM_BYTES_W(32)>>>(
        pxc2, m2_xp_w, nullptr, pdbl2, BATCH * CH, DBL2, D2I / 16, D2I, D2I, DBL2);
    // dt2: delta2[256, 8192] = softplus(dbl2[:, :256] @ dt_w^T + b)
    tf32_gemm<2, 32><<<dim3(64, 2, 1), 256, GSMEM_BYTES_W(32)>>>(
        pdbl2, m2_dt_w, m2_dt_b, pdelta2, BATCH * CH, D2I, DT2R, DBL2, DT2R, D2I);
    scan2_kernel<<<BATCH * (D2I / 256), T>>>(pdelta2, pxc2, pdbl2, m2_Alog, m2_D, pxz2, py2);
    // out2: out2[256, 4096] split-K=4 atomic
    tf32_gemm<1, 64><<<dim3(16, 2, 4), 256, GSMEM_BYTES_W(64)>>>(
        py2, m2_out_w, nullptr, pout2, BATCH * CH, D2M, D2I / 4, D2I, D2I, D2M);

    // ---- combine ----
    combine_kernel<<<(BATCH * CH * LL + T - 1) / T, T>>>(x, out);
}

// round 5
// speedup vs baseline: 1.0898x; 1.0898x over previous
#include <cuda_runtime.h>
#include <cstdint>
#include <math.h>

// ---------------- problem constants ----------------
#define BATCH 2
#define CH    128
#define LL    4096
#define NS    8

#define D1M  128
#define D1I  256
#define DT1R 8
#define DBL1 24
#define D2M  4096
#define D2I  8192
#define DT2R 256
#define DBL2 272      // dt_rank(256) + 2*8

#define NCH  32
#define CLEN 128

// ---------------- scratch ----------------
__device__ __align__(16) float g_xn1[BATCH*LL*D1M];
__device__ __align__(16) float g_xz1[BATCH*LL*2*D1I];
__device__ __align__(16) float g_xc1[BATCH*LL*D1I];
__device__ __align__(16) float g_dbl1[BATCH*LL*DBL1];
__device__ __align__(16) float g_delta1[BATCH*LL*D1I];
__device__ __align__(16) float g_y1[BATCH*LL*D1I];
__device__ __align__(16) float g_out1[BATCH*LL*D1M];
__device__ __align__(16) float g_ckP[BATCH*D1I*NCH*NS];
__device__ __align__(16) float g_ckH[BATCH*D1I*NCH*NS];
__device__ __align__(16) float g_hin[BATCH*D1I*NCH*NS];

__device__ __align__(16) float g_xn2[BATCH*CH*D2M];
__device__ __align__(16) float g_xz2[BATCH*CH*2*D2I];
__device__ __align__(16) float g_xc2[BATCH*CH*D2I];
__device__ __align__(16) float g_dbl2[BATCH*CH*DBL2];
__device__ __align__(16) float g_delta2[BATCH*CH*D2I];
__device__ __align__(16) float g_y2[BATCH*CH*D2I];
__device__ __align__(16) float g_out2[BATCH*CH*D2M];

// ---------------- helpers ----------------
__device__ __forceinline__ uint32_t smem_u32(const void* p) {
    uint32_t a;
    asm("{ .reg .u64 t; cvta.to.shared.u64 t, %1; cvt.u32.u64 %0, t; }" : "=r"(a) : "l"(p));
    return a;
}
__device__ __forceinline__ void cp_async16(uint32_t dst, const void* src, int sz) {
    asm volatile("cp.async.cg.shared.global [%0], [%1], 16, %2;"
                 :: "r"(dst), "l"(src), "r"(sz) : "memory");
}
#define CP_COMMIT() asm volatile("cp.async.commit_group;" ::: "memory")
#define CP_WAIT2()  asm volatile("cp.async.wait_group 2;" ::: "memory")
#define CP_WAIT1()  asm volatile("cp.async.wait_group 1;" ::: "memory")
#define CP_WAIT0()  asm volatile("cp.async.wait_group 0;" ::: "memory")

__device__ __forceinline__ uint32_t f2tf32(float f) {
    uint32_t r;
    asm("cvt.rna.tf32.f32 %0, %1;" : "=r"(r) : "f"(f));
    return r;
}
__device__ __forceinline__ float rnd_tf32(float v) { return __uint_as_float(f2tf32(v)); }

__device__ __forceinline__ void mma_tf32(float* d, const uint32_t* a, const uint32_t* b) {
    asm volatile(
        "mma.sync.aligned.m16n8k8.row.col.f32.tf32.tf32.f32 "
        "{%0,%1,%2,%3}, {%4,%5,%6,%7}, {%8,%9}, {%0,%1,%2,%3};"
        : "+f"(d[0]), "+f"(d[1]), "+f"(d[2]), "+f"(d[3])
        : "r"(a[0]), "r"(a[1]), "r"(a[2]), "r"(a[3]), "r"(b[0]), "r"(b[1]));
}

__device__ __forceinline__ float siluf(float v) { return v / (1.f + __expf(-v)); }
__device__ __forceinline__ float softplusf(float v) { return (v > 20.f) ? v : log1pf(__expf(v)); }

// ======================================================================
// tf32 mma.sync GEMM: C[m, n] = sum_k X[m, k] * W[n, k]
// A-side (X, activations) pre-rounded to tf32 at the producer.
// BM=128, BN=128; warp grid 2x4, warp tile 64x32. 4-stage cp.async,
// single __syncthreads per K-iter (compute-then-load ordering).
// grid = (N/128 tiles, M/128 tiles, ksplits); block = 256 threads
// EPI: 0 = store, 1 = atomicAdd (split-K), 2 = softplus(v + bias[n]) store
// ======================================================================
#define SROW 36
#define GROWS 256                       // 128 A rows + 128 B rows per stage
#define GSTG (GROWS * SROW)             // floats per stage
#define GSMEM_BYTES (4 * GSTG * 4)      // 144 KB

template<int EPI>
__global__ void __launch_bounds__(256, 1)
tf32_gemm(const float* __restrict__ X, const float* __restrict__ W,
          const float* __restrict__ bias, float* __restrict__ C,
          int M, int N, int kLen, int ldx, int ldw, int ldc) {
    extern __shared__ float sm[];
    const int tid = threadIdx.x;
    const int wid = tid >> 5, lane = tid & 31;
    const int gid = lane >> 2, tig = lane & 3;
    const int wm = wid >> 2, wn = wid & 3;        // 2 x 4 warp grid
    const int m0 = blockIdx.y * 128, n0 = blockIdx.x * 128;
    const long k0 = (long)blockIdx.z * kLen;
    const int nIter = kLen / 32;
    const uint32_t sS = smem_u32(sm);

    float acc[4][4][4];
    #pragma unroll
    for (int i = 0; i < 4; i++)
        #pragma unroll
        for (int j = 0; j < 4; j++)
            #pragma unroll
            for (int r = 0; r < 4; r++) acc[i][j][r] = 0.f;

    auto load_stage = [&](int buf, long kk) {
        #pragma unroll
        for (int i = 0; i < 8; i++) {
            int idx = tid + i * 256;           // 0..2047
            int row = idx >> 3, ch = idx & 7;
            uint32_t off = (uint32_t)((buf * GROWS + row) * SROW + ch * 4) * 4u;
            if (row < 128) {
                cp_async16(sS + off, X + (long)(m0 + row) * ldx + kk + ch * 4, 16);
            } else {
                int nr = n0 + row - 128;
                const float* gb = W + (long)(nr < N ? nr : 0) * ldw + kk + ch * 4;
                cp_async16(sS + off, gb, nr < N ? 16 : 0);
            }
        }
    };

    load_stage(0, k0); CP_COMMIT();
    load_stage(1, k0 + 32); CP_COMMIT();
    load_stage(2, k0 + 64); CP_COMMIT();

    for (int it = 0; it < nIter; it++) {
        if (it + 2 < nIter) { CP_WAIT2(); }
        else if (it + 1 < nIter) { CP_WAIT1(); }
        else { CP_WAIT0(); }
        __syncthreads();

        const float* A  = sm + (it & 3) * GSTG;
        const float* Bp = A + 128 * SROW;
        #pragma unroll
        for (int ks = 0; ks < 4; ks++) {
            uint32_t a[4][4], b[4][2];
            const int kc = ks * 8 + tig;
            #pragma unroll
            for (int mi = 0; mi < 4; mi++) {
                int r = wm * 64 + mi * 16 + gid;
                a[mi][0] = __float_as_uint(A[r * SROW + kc]);
                a[mi][1] = __float_as_uint(A[(r + 8) * SROW + kc]);
                a[mi][2] = __float_as_uint(A[r * SROW + kc + 4]);
                a[mi][3] = __float_as_uint(A[(r + 8) * SROW + kc + 4]);
            }
            #pragma unroll
            for (int ni = 0; ni < 4; ni++) {
                int rn = wn * 32 + ni * 8 + gid;
                b[ni][0] = f2tf32(Bp[rn * SROW + kc]);
                b[ni][1] = f2tf32(Bp[rn * SROW + kc + 4]);
            }
            #pragma unroll
            for (int mi = 0; mi < 4; mi++)
                #pragma unroll
                for (int ni = 0; ni < 4; ni++)
                    mma_tf32(acc[mi][ni], a[mi], b[ni]);
        }
        // load AFTER compute: writes go to (it+3)&3, reads were (it)&3 — disjoint
        if (it + 3 < nIter) { load_stage((it + 3) & 3, k0 + (long)(it + 3) * 32); CP_COMMIT(); }
    }

    // epilogue
    #pragma unroll
    for (int mi = 0; mi < 4; mi++) {
        int m = m0 + wm * 64 + mi * 16 + gid;
        #pragma unroll
        for (int ni = 0; ni < 4; ni++) {
            int n = n0 + wn * 32 + ni * 8 + tig * 2;
            if (n >= N) continue;
            float* p0 = C + (long)m * ldc + n;
            float* p1 = C + (long)(m + 8) * ldc + n;
            float c0 = acc[mi][ni][0], c1 = acc[mi][ni][1];
            float c2 = acc[mi][ni][2], c3 = acc[mi][ni][3];
            if (EPI == 1) {
                atomicAdd(p0, c0); atomicAdd(p0 + 1, c1);
                atomicAdd(p1, c2); atomicAdd(p1 + 1, c3);
            } else if (EPI == 2) {
                float b0v = bias[n], b1v = bias[n + 1];
                *reinterpret_cast<float2*>(p0) =
                    make_float2(softplusf(c0 + b0v), softplusf(c1 + b1v));
                *reinterpret_cast<float2*>(p1) =
                    make_float2(softplusf(c2 + b0v), softplusf(c3 + b1v));
            } else {
                *reinterpret_cast<float2*>(p0) = make_float2(c0, c1);
                *reinterpret_cast<float2*>(p1) = make_float2(c2, c3);
            }
        }
    }
}

// ---------------- LayerNorm 1 (output tf32-rounded) ----------------
__global__ void ln1_kernel(const float* __restrict__ x, const float* __restrict__ g,
                           const float* __restrict__ bta, float* __restrict__ out) {
    int b  = blockIdx.x >> 7;
    int l0 = (blockIdx.x & 127) * 32;
    __shared__ float sm[128 * 33];
    int tid = threadIdx.x;
    #pragma unroll
    for (int i = 0; i < 16; i++) {
        int idx = tid + i * 256;
        int c = idx >> 5, l = idx & 31;
        sm[c * 33 + l] = x[((long)b * CH + c) * LL + l0 + l];
    }
    __syncthreads();
    int warp = tid >> 5, lane = tid & 31;
    for (int t = warp; t < 32; t += 8) {
        float v[4]; float s = 0.f, sq = 0.f;
        #pragma unroll
        for (int j = 0; j < 4; j++) {
            v[j] = sm[(lane + 32 * j) * 33 + t];
            s += v[j]; sq += v[j] * v[j];
        }
        #pragma unroll
        for (int o = 16; o; o >>= 1) {
            s  += __shfl_xor_sync(0xffffffffu, s,  o);
            sq += __shfl_xor_sync(0xffffffffu, sq, o);
        }
        float mu  = s * (1.f / 128.f);
        float var = sq * (1.f / 128.f) - mu * mu;
        float rs  = rsqrtf(var + 1e-5f);
        #pragma unroll
        for (int j = 0; j < 4; j++) {
            int c = lane + 32 * j;
            out[((long)b * LL + l0 + t) * D1M + c] = rnd_tf32((v[j] - mu) * rs * g[c] + bta[c]);
        }
    }
}

// ---------------- LayerNorm 2 (output tf32-rounded) ----------------
__global__ void ln2_kernel(const float* __restrict__ x, const float* __restrict__ g,
                           const float* __restrict__ bta, float* __restrict__ out) {
    long row = blockIdx.x;
    const float* xr = x + row * D2M;
    float* orow = out + row * D2M;
    int tid = threadIdx.x;
    float v[16]; float s = 0.f, sq = 0.f;
    #pragma unroll
    for (int i = 0; i < 16; i++) {
        v[i] = xr[i * 256 + tid];
        s += v[i]; sq += v[i] * v[i];
    }
    #pragma unroll
    for (int o = 16; o; o >>= 1) {
        s  += __shfl_xor_sync(0xffffffffu, s,  o);
        sq += __shfl_xor_sync(0xffffffffu, sq, o);
    }
    __shared__ float ss[8], sqq[8];
    int lane = tid & 31, warp = tid >> 5;
    if (!lane) { ss[warp] = s; sqq[warp] = sq; }
    __syncthreads();
    s = 0.f; sq = 0.f;
    #pragma unroll
    for (int w = 0; w < 8; w++) { s += ss[w]; sq += sqq[w]; }
    float mu  = s * (1.f / 4096.f);
    float var = sq * (1.f / 4096.f) - mu * mu;
    float rs  = rsqrtf(var + 1e-5f);
    #pragma unroll
    for (int i = 0; i < 16; i++) {
        int col = i * 256 + tid;
        orow[col] = rnd_tf32((v[i] - mu) * rs * g[col] + bta[col]);
    }
}

// ---------------- fallback SGEMM (dt1: K=8) ----------------
template<int ACT, bool HASBIAS>
__global__ void sgemm_kernel(const float* __restrict__ X, const float* __restrict__ W,
                             const float* __restrict__ bias, float* __restrict__ out,
                             int M, int N, int K, int lda, int ldc) {
    constexpr int BM = 64, BN = 64, BK = 32, PAD = 4;
    __shared__ float As[BK][BM + PAD];
    __shared__ float Bs[BK][BN + PAD];
    int bm = blockIdx.y * BM, bn = blockIdx.x * BN;
    int tid = threadIdx.x;
    int tx = tid & 15, ty = tid >> 4;
    float acc[4][4] = {};
    for (int k0 = 0; k0 < K; k0 += BK) {
        #pragma unroll
        for (int i = 0; i < 2; i++) {
            int idx = tid + i * 256;
            int row = idx >> 3;
            int kc  = (idx & 7) << 2;
            int k   = k0 + kc;
            float4 va = make_float4(0.f, 0.f, 0.f, 0.f);
            float4 vb = make_float4(0.f, 0.f, 0.f, 0.f);
            if (k < K) {
                int m = bm + row;
                if (m < M) va = *reinterpret_cast<const float4*>(X + (long)m * lda + k);
                int n = bn + row;
                if (n < N) vb = *reinterpret_cast<const float4*>(W + (long)n * K + k);
            }
            As[kc][row] = va.x; As[kc + 1][row] = va.y; As[kc + 2][row] = va.z; As[kc + 3][row] = va.w;
            Bs[kc][row] = vb.x; Bs[kc + 1][row] = vb.y; Bs[kc + 2][row] = vb.z; Bs[kc + 3][row] = vb.w;
        }
        __syncthreads();
        #pragma unroll
        for (int kk = 0; kk < BK; kk++) {
            float4 a = *reinterpret_cast<const float4*>(&As[kk][ty << 2]);
            float4 b = *reinterpret_cast<const float4*>(&Bs[kk][tx << 2]);
            float av[4] = {a.x, a.y, a.z, a.w};
            float bv[4] = {b.x, b.y, b.z, b.w};
            #pragma unroll
            for (int i = 0; i < 4; i++)
                #pragma unroll
                for (int j = 0; j < 4; j++)
                    acc[i][j] += av[i] * bv[j];
        }
        __syncthreads();
    }
    #pragma unroll
    for (int i = 0; i < 4; i++) {
        int m = bm + (ty << 2) + i;
        if (m >= M) continue;
        #pragma unroll
        for (int j = 0; j < 4; j++) {
            int n = bn + (tx << 2) + j;
            if (n >= N) continue;
            float v = acc[i][j];
            if (HASBIAS) v += bias[n];
            if (ACT == 1) v = softplusf(v);
            out[(long)m * ldc + n] = v;
        }
    }
}

// ---------------- causal depthwise conv (K=4) + SiLU, float4-vectorized ----------------
__global__ void conv_silu_kernel(const float* __restrict__ xz, const float* __restrict__ w,
                                 const float* __restrict__ bias, float* __restrict__ out,
                                 int Ltok, int dinner) {
    long tid = (long)blockIdx.x * 256 + threadIdx.x;     // one thread = 4 channels
    long total = (long)BATCH * Ltok * (dinner / 4);
    if (tid >= total) return;
    int d4 = (int)(tid % (dinner / 4)) * 4;
    long t = tid / (dinner / 4);
    int l = (int)(t % Ltok);
    int b = (int)(t / Ltok);
    int rowstride = 2 * dinner;
    const float* base = xz + ((long)b * Ltok + l) * rowstride + d4;
    float4 bv = *reinterpret_cast<const float4*>(bias + d4);
    float acc0 = bv.x, acc1 = bv.y, acc2 = bv.z, acc3 = bv.w;
    #pragma unroll
    for (int k = 0; k < 4; k++) {
        int ll = l - 3 + k;
        if (ll >= 0) {
            float4 xv = *reinterpret_cast<const float4*>(base + (long)(ll - l) * rowstride);
            acc0 += xv.x * w[(d4 + 0) * 4 + k];
            acc1 += xv.y * w[(d4 + 1) * 4 + k];
            acc2 += xv.z * w[(d4 + 2) * 4 + k];
            acc3 += xv.w * w[(d4 + 3) * 4 + k];
        }
    }
    float4 ov;
    ov.x = rnd_tf32(siluf(acc0)); ov.y = rnd_tf32(siluf(acc1));
    ov.z = rnd_tf32(siluf(acc2)); ov.w = rnd_tf32(siluf(acc3));
    *reinterpret_cast<float4*>(out + ((long)b * Ltok + l) * dinner + d4) = ov;
}

// ---------------- path-1 scan ----------------
__global__ void scan1_partial(const float* __restrict__ delta, const float* __restrict__ xc,
                              const float* __restrict__ dbl, const float* __restrict__ Alog) {
    int d = threadIdx.x;
    int chunk = blockIdx.x & (NCH - 1);
    int b = blockIdx.x >> 5;
    float A[NS], h[NS], P[NS];
    #pragma unroll
    for (int s = 0; s < NS; s++) { A[s] = -__expf(Alog[d * NS + s]); h[s] = 0.f; P[s] = 1.f; }
    int l0 = chunk * CLEN;
    for (int i = 0; i < CLEN; i++) {
        long t = (long)b * LL + l0 + i;
        float dl = delta[t * D1I + d];
        float xv = xc[t * D1I + d];
        const float* bl = dbl + t * DBL1 + DT1R;
        float dx = dl * xv;
        #pragma unroll
        for (int s = 0; s < NS; s++) {
            float dA = __expf(dl * A[s]);
            h[s] = dA * h[s] + dx * bl[s];
            P[s] *= dA;
        }
    }
    long o = (((long)b * D1I + d) * NCH + chunk) * NS;
    #pragma unroll
    for (int s = 0; s < NS; s++) { g_ckP[o + s] = P[s]; g_ckH[o + s] = h[s]; }
}

__global__ void scan1_carry() {
    int idx = blockIdx.x * 256 + threadIdx.x;
    if (idx >= BATCH * D1I) return;
    long base = (long)idx * NCH * NS;
    float h[NS];
    #pragma unroll
    for (int s = 0; s < NS; s++) h[s] = 0.f;
    for (int c = 0; c < NCH; c++) {
        long o = base + (long)c * NS;
        #pragma unroll
        for (int s = 0; s < NS; s++) {
            g_hin[o + s] = h[s];
            h[s] = g_ckP[o + s] * h[s] + g_ckH[o + s];
        }
    }
}

__global__ void scan1_final(const float* __restrict__ delta, const float* __restrict__ xc,
                            const float* __restrict__ dbl, const float* __restrict__ Alog,
                            const float* __restrict__ Dp, const float* __restrict__ xz,
                            float* __restrict__ y) {
    int d = threadIdx.x;
    int chunk = blockIdx.x & (NCH - 1);
    int b = blockIdx.x >> 5;
    float A[NS], h[NS];
    long hb = (((long)b * D1I + d) * NCH + chunk) * NS;
    #pragma unroll
    for (int s = 0; s < NS; s++) { A[s] = -__expf(Alog[d * NS + s]); h[s] = g_hin[hb + s]; }
    float Dv = Dp[d];
    int l0 = chunk * CLEN;
    for (int i = 0; i < CLEN; i++) {
        long t = (long)b * LL + l0 + i;
        float dl = delta[t * D1I + d];
        float xv = xc[t * D1I + d];
        const float* bl = dbl + t * DBL1 + DT1R;
        float dx = dl * xv;
        float acc = 0.f;
        #pragma unroll
        for (int s = 0; s < NS; s++) {
            float dA = __expf(dl * A[s]);
            h[s] = dA * h[s] + dx * bl[s];
            acc += h[s] * bl[NS + s];
        }
        float z = xz[t * (2 * D1I) + D1I + d];
        y[t * D1I + d] = rnd_tf32((acc + xv * Dv) * siluf(z));
    }
}

// ---------------- path-2 scan ----------------
__global__ void scan2_kernel(const float* __restrict__ delta, const float* __restrict__ xc,
                             const float* __restrict__ dbl, const float* __restrict__ Alog,
                             const float* __restrict__ Dp, const float* __restrict__ xz,
                             float* __restrict__ y) {
    int d = (blockIdx.x & 31) * 256 + threadIdx.x;
    int b = blockIdx.x >> 5;
    float A[NS], h[NS];
    #pragma unroll
    for (int s = 0; s < NS; s++) { A[s] = -__expf(Alog[d * NS + s]); h[s] = 0.f; }
    float Dv = Dp[d];
    for (int l = 0; l < CH; l++) {
        long t = (long)b * CH + l;
        float dl = delta[t * D2I + d];
        float xv = xc[t * D2I + d];
        const float* bl = dbl + t * DBL2 + DT2R;
        float dx = dl * xv;
        float acc = 0.f;
        #pragma unroll
        for (int s = 0; s < NS; s++) {
            float dA = __expf(dl * A[s]);
            h[s] = dA * h[s] + dx * bl[s];
            acc += h[s] * bl[NS + s];
        }
        float z = xz[t * (2 * D2I) + D2I + d];
        y[t * D2I + d] = rnd_tf32((acc + xv * Dv) * siluf(z));
    }
}

// ---------------- combine ----------------
__global__ void combine_kernel(const float* __restrict__ x, float* __restrict__ out) {
    long i = (long)blockIdx.x * 256 + threadIdx.x;
    if (i >= (long)BATCH * CH * LL) return;
    int l = (int)(i % LL);
    long t = i / LL;
    int c = (int)(t % CH);
    int b = (int)(t / CH);
    out[i] = x[i] + g_out2[i] + g_out1[((long)b * LL + l) * D1M + c];
}

// ---------------- launch ----------------
extern "C" void kernel_launch(void* const* d_in, const int* in_sizes, int n_in,
                              void* d_out, int out_size) {
    const float* x        = (const float*)d_in[0];
    const float* ln1_g    = (const float*)d_in[1];
    const float* ln1_b    = (const float*)d_in[2];
    const float* ln2_g    = (const float*)d_in[3];
    const float* ln2_b    = (const float*)d_in[4];
    const float* m1_in_w  = (const float*)d_in[5];
    const float* m1_cw    = (const float*)d_in[6];
    const float* m1_cb    = (const float*)d_in[7];
    const float* m1_xp_w  = (const float*)d_in[8];
    const float* m1_dt_w  = (const float*)d_in[9];
    const float* m1_dt_b  = (const float*)d_in[10];
    const float* m1_Alog  = (const float*)d_in[11];
    const float* m1_D     = (const float*)d_in[12];
    const float* m1_out_w = (const float*)d_in[13];
    const float* m2_in_w  = (const float*)d_in[14];
    const float* m2_cw    = (const float*)d_in[15];
    const float* m2_cb    = (const float*)d_in[16];
    const float* m2_xp_w  = (const float*)d_in[17];
    const float* m2_dt_w  = (const float*)d_in[18];
    const float* m2_dt_b  = (const float*)d_in[19];
    const float* m2_Alog  = (const float*)d_in[20];
    const float* m2_D     = (const float*)d_in[21];
    const float* m2_out_w = (const float*)d_in[22];
    float* out = (float*)d_out;

    float *pxn1, *pxz1, *pxc1, *pdbl1, *pdelta1, *py1, *pout1;
    float *pxn2, *pxz2, *pxc2, *pdbl2, *pdelta2, *py2, *pout2;
    cudaGetSymbolAddress((void**)&pxn1, g_xn1);
    cudaGetSymbolAddress((void**)&pxz1, g_xz1);
    cudaGetSymbolAddress((void**)&pxc1, g_xc1);
    cudaGetSymbolAddress((void**)&pdbl1, g_dbl1);
    cudaGetSymbolAddress((void**)&pdelta1, g_delta1);
    cudaGetSymbolAddress((void**)&py1, g_y1);
    cudaGetSymbolAddress((void**)&pout1, g_out1);
    cudaGetSymbolAddress((void**)&pxn2, g_xn2);
    cudaGetSymbolAddress((void**)&pxz2, g_xz2);
    cudaGetSymbolAddress((void**)&pxc2, g_xc2);
    cudaGetSymbolAddress((void**)&pdbl2, g_dbl2);
    cudaGetSymbolAddress((void**)&pdelta2, g_delta2);
    cudaGetSymbolAddress((void**)&py2, g_y2);
    cudaGetSymbolAddress((void**)&pout2, g_out2);

    cudaFuncSetAttribute(tf32_gemm<0>, cudaFuncAttributeMaxDynamicSharedMemorySize, GSMEM_BYTES);
    cudaFuncSetAttribute(tf32_gemm<1>, cudaFuncAttributeMaxDynamicSharedMemorySize, GSMEM_BYTES);
    cudaFuncSetAttribute(tf32_gemm<2>, cudaFuncAttributeMaxDynamicSharedMemorySize, GSMEM_BYTES);

    const int T = 256;
    // launch 0,1: split-K accumulators
    cudaMemsetAsync(pdbl2, 0, sizeof(float) * BATCH * CH * DBL2);
    cudaMemsetAsync(pout2, 0, sizeof(float) * BATCH * CH * D2M);
    // launch 2,3
    ln1_kernel<<<BATCH * (LL / 32), T>>>(x, ln1_g, ln1_b, pxn1);
    ln2_kernel<<<BATCH * CH, T>>>(x, ln2_g, ln2_b, pxn2);
    // launch 4: in1: xz1[8192, 512] = xn1 @ in_w^T
    tf32_gemm<0><<<dim3(4, 64, 1), 256, GSMEM_BYTES>>>(
        pxn1, m1_in_w, nullptr, pxz1, BATCH * LL, 2 * D1I, D1M, D1M, D1M, 2 * D1I);
    // launch 5 (PROFILED): in2: xz2[256, 16384] = xn2 @ in_w^T  (256 CTAs)
    tf32_gemm<0><<<dim3(128, 2, 1), 256, GSMEM_BYTES>>>(
        pxn2, m2_in_w, nullptr, pxz2, BATCH * CH, 2 * D2I, D2M, D2M, D2M, 2 * D2I);

    // ---- rest of path 1 ----
    conv_silu_kernel<<<(BATCH * LL * D1I / 4 + T - 1) / T, T>>>(pxz1, m1_cw, m1_cb, pxc1, LL, D1I);
    tf32_gemm<0><<<dim3(1, 64, 1), 256, GSMEM_BYTES>>>(
        pxc1, m1_xp_w, nullptr, pdbl1, BATCH * LL, DBL1, D1I, D1I, D1I, DBL1);
    sgemm_kernel<1, true><<<dim3((D1I + 63) / 64, (BATCH * LL) / 64), T>>>(
        pdbl1, m1_dt_w, m1_dt_b, pdelta1, BATCH * LL, D1I, DT1R, DBL1, D1I);
    scan1_partial<<<BATCH * NCH, D1I>>>(pdelta1, pxc1, pdbl1, m1_Alog);
    scan1_carry<<<(BATCH * D1I + T - 1) / T, T>>>();
    scan1_final<<<BATCH * NCH, D1I>>>(pdelta1, pxc1, pdbl1, m1_Alog, m1_D, pxz1, py1);
    tf32_gemm<0><<<dim3(1, 64, 1), 256, GSMEM_BYTES>>>(
        py1, m1_out_w, nullptr, pout1, BATCH * LL, D1M, D1I, D1I, D1I, D1M);

    // ---- rest of path 2 ----
    conv_silu_kernel<<<(BATCH * CH * D2I / 4 + T - 1) / T, T>>>(pxz2, m2_cw, m2_cb, pxc2, CH, D2I);
    // xp2: dbl2[256, 272] split-K=16 atomic (96 CTAs)
    tf32_gemm<1><<<dim3(3, 2, 16), 256, GSMEM_BYTES>>>(
        pxc2, m2_xp_w, nullptr, pdbl2, BATCH * CH, DBL2, D2I / 16, D2I, D2I, DBL2);
    // dt2: delta2[256, 8192] = softplus(dbl2[:, :256] @ dt_w^T + b) (128 CTAs)
    tf32_gemm<2><<<dim3(64, 2, 1), 256, GSMEM_BYTES>>>(
        pdbl2, m2_dt_w, m2_dt_b, pdelta2, BATCH * CH, D2I, DT2R, DBL2, DT2R, D2I);
    scan2_kernel<<<BATCH * (D2I / 256), T>>>(pdelta2, pxc2, pdbl2, m2_Alog, m2_D, pxz2, py2);
    // out2: out2[256, 4096] split-K=4 atomic (256 CTAs)
    tf32_gemm<1><<<dim3(32, 2, 4), 256, GSMEM_BYTES>>>(
        py2, m2_out_w, nullptr, pout2, BATCH * CH, D2M, D2I / 4, D2I, D2I, D2M);

    // ---- combine ----
    combine_kernel<<<(BATCH * CH * LL + T - 1) / T, T>>>(x, out);
}